// round 8
// baseline (speedup 1.0000x reference)
#include <cuda_runtime.h>

#define CCH 32
#define HH  256
#define WW  512
#define KK  10
#define HWPIX (HH*WW)

// Transposed [H,W,C] copy of right (channels contiguous) — static scratch.
__device__ float g_right_t[HWPIX * CCH];

// [C,H,W] -> [H,W,C], float4 on both global sides.
__global__ __launch_bounds__(1024) void transpose_chw_hwc(const float* __restrict__ right) {
    __shared__ float tile[32][129];
    const int h  = blockIdx.y;
    const int w0 = blockIdx.x * 128;
    const int tx = threadIdx.x, ty = threadIdx.y;

    const float4 v = *(const float4*)(right + (size_t)ty * HWPIX + h * WW + w0 + 4 * tx);
    tile[ty][4*tx + 0] = v.x;
    tile[ty][4*tx + 1] = v.y;
    tile[ty][4*tx + 2] = v.z;
    tile[ty][4*tx + 3] = v.w;
    __syncthreads();

    const int t  = ty * 32 + tx;
    const int wl = t >> 3;
    const int cq = t & 7;
    float4 o;
    o.x = tile[4*cq + 0][wl];
    o.y = tile[4*cq + 1][wl];
    o.z = tile[4*cq + 2][wl];
    o.w = tile[4*cq + 3][wl];
    *(float4*)(g_right_t + (size_t)(h * WW + w0 + wl) * CCH + 4 * cq) = o;
}

// Broadcast offset plane p (0..9 = ox, 10..19 = oy) from this 8-lane group's regs.
#define BCASTV(r0, r1, r2, p) __shfl_sync(0xffffffffu,                         \
    ((p) < 8 ? (r0) : ((p) < 16 ? (r1) : (r2))), (lane & 24) | ((p) & 7))

// Bilinear gather + per-lane 4-channel L1 cost for one pixel.
__device__ __forceinline__ float gather_cost(
    const float4* __restrict__ rt, int j, float wfl, float hfl,
    float ox_k, float oy_k, float lv0, float lv1, float lv2, float lv3)
{
    // clip->normalize->unnormalize == r-0.5 exactly in fp32;
    // offset_x >= 0 so the upper x-clamp is a no-op.
    const float rx = fmaxf(wfl - ox_k, 0.0f);
    const float ry = fminf(fmaxf(hfl - oy_k, 0.0f), (float)HH - 1.0f);
    const float ix = rx - 0.5f, iy = ry - 0.5f;
    const float x0f = floorf(ix), y0f = floorf(iy);
    const int x0 = (int)x0f, y0 = (int)y0f;           // >= -1
    const float wx1 = ix - x0f, wy1 = iy - y0f;
    float wx0 = 1.0f - wx1, wy0 = 1.0f - wy1;
    if (x0 < 0) wx0 = 0.0f;                           // only low edge invalid
    if (y0 < 0) wy0 = 0.0f;
    const int x0c = max(x0, 0), y0c = max(y0, 0);
    const int x1 = x0 + 1, y1 = y0 + 1;               // always in range
    const float w00 = wx0*wy0, w01 = wx1*wy0, w10 = wx0*wy1, w11 = wx1*wy1;

    const float4 g00 = rt[(y0c * WW + x0c) * 8 + j];
    const float4 g01 = rt[(y0c * WW + x1 ) * 8 + j];
    const float4 g10 = rt[(y1  * WW + x0c) * 8 + j];
    const float4 g11 = rt[(y1  * WW + x1 ) * 8 + j];

    const float t0 = w00*g00.x + w01*g01.x + w10*g10.x + w11*g11.x;
    const float t1 = w00*g00.y + w01*g01.y + w10*g10.y + w11*g11.y;
    const float t2 = w00*g00.z + w01*g01.z + w10*g10.z + w11*g11.z;
    const float t3 = w00*g00.w + w01*g01.w + w10*g10.w + w11*g11.w;
    return fabsf(lv0 - t0) + fabsf(lv1 - t1) + fabsf(lv2 - t2) + fabsf(lv3 - t3);
}

__global__ __launch_bounds__(256) void eval_kernel(
    const float* __restrict__ left,
    const float* __restrict__ offx,
    const float* __restrict__ offy,
    float* __restrict__ out)
{
    // [warp][pixel-in-warp][k] : (s, ox, oy, pad)
    __shared__ float4 s_sm[8 * 8 * KK];

    const int lane = threadIdx.x & 31;
    const int j    = lane & 7;            // channel quad within pixel
    const int g    = lane >> 3;           // pixel subgroup 0..3
    const int warp = threadIdx.x >> 5;
    const int base = blockIdx.x * 64 + warp * 8;   // 8 pixels per warp, same row
    const int pixA = base + g;
    const int pixB = base + 4 + g;
    const int h    = base >> 9;                    // identical for A and B
    const float hfl  = (float)h;
    const float wflA = (float)(pixA & (WW - 1));
    const float wflB = wflA + 4.0f;

    // left channels 4j..4j+3 for both pixels
    const float lA0 = left[(4*j + 0) * HWPIX + pixA];
    const float lA1 = left[(4*j + 1) * HWPIX + pixA];
    const float lA2 = left[(4*j + 2) * HWPIX + pixA];
    const float lA3 = left[(4*j + 3) * HWPIX + pixA];
    const float lB0 = left[(4*j + 0) * HWPIX + pixB];
    const float lB1 = left[(4*j + 1) * HWPIX + pixB];
    const float lB2 = left[(4*j + 2) * HWPIX + pixB];
    const float lB3 = left[(4*j + 3) * HWPIX + pixB];

    // 20 offset planes per pixel, distributed over the 8-lane group
    const float a0 = offx[j * HWPIX + pixA];
    const float a1 = (j < 2) ? offx[(j + 8) * HWPIX + pixA]
                             : offy[(j - 2) * HWPIX + pixA];
    const float a2 = (j < 4) ? offy[(j + 6) * HWPIX + pixA] : 0.0f;
    const float b0 = offx[j * HWPIX + pixB];
    const float b1 = (j < 2) ? offx[(j + 8) * HWPIX + pixB]
                             : offy[(j - 2) * HWPIX + pixB];
    const float b2 = (j < 4) ? offy[(j + 6) * HWPIX + pixB] : 0.0f;

    const float4* __restrict__ rt = (const float4*)g_right_t;

    #pragma unroll
    for (int k = 0; k < KK; k++) {
        const float oxA = BCASTV(a0, a1, a2, k);
        const float oyA = BCASTV(a0, a1, a2, k + KK);
        const float oxB = BCASTV(b0, b1, b2, k);
        const float oyB = BCASTV(b0, b1, b2, k + KK);

        float dA = gather_cost(rt, j, wflA, hfl, oxA, oyA, lA0, lA1, lA2, lA3);
        float dB = gather_cost(rt, j, wflB, hfl, oxB, oyB, lB0, lB1, lB2, lB3);

        dA += __shfl_xor_sync(0xffffffffu, dA, 4);
        dB += __shfl_xor_sync(0xffffffffu, dB, 4);
        dA += __shfl_xor_sync(0xffffffffu, dA, 2);
        dB += __shfl_xor_sync(0xffffffffu, dB, 2);
        dA += __shfl_xor_sync(0xffffffffu, dA, 1);
        dB += __shfl_xor_sync(0xffffffffu, dB, 1);

        if (j == 0) {
            s_sm[warp * 80 +      g * KK + k] =
                make_float4(dA * (-10000.0f / 32.0f), oxA, oyA, 0.0f);
            s_sm[warp * 80 + 40 + g * KK + k] =
                make_float4(dB * (-10000.0f / 32.0f), oxB, oyB, 0.0f);
        }
    }

    __syncwarp();

    // epilogue: lane l (< 8) owns pixel base+l entirely
    if (lane < 8) {
        float4 v[KK];
        #pragma unroll
        for (int k = 0; k < KK; k++)
            v[k] = s_sm[warp * 80 + lane * KK + k];

        float m = v[0].x;
        #pragma unroll
        for (int k = 1; k < KK; k++) m = fmaxf(m, v[k].x);
        float denom = 0.0f, oxa = 0.0f, oya = 0.0f;
        #pragma unroll
        for (int k = 0; k < KK; k++) {
            const float e = __expf(v[k].x - m);
            denom += e;
            oxa   += e * v[k].y;
            oya   += e * v[k].z;
        }
        const float inv = 1.0f / denom;
        const int opix = base + lane;
        out[opix]         = oxa * inv;
        out[HWPIX + opix] = oya * inv;
    }
}

extern "C" void kernel_launch(void* const* d_in, const int* in_sizes, int n_in,
                              void* d_out, int out_size) {
    const float* left  = (const float*)d_in[0];
    const float* right = (const float*)d_in[1];
    const float* offx  = (const float*)d_in[2];
    const float* offy  = (const float*)d_in[3];
    float* out = (float*)d_out;

    dim3 tb(32, 32);
    dim3 tg(WW / 128, HH);
    transpose_chw_hwc<<<tg, tb>>>(right);

    // 256 threads = 8 warps = 64 pixels per block
    eval_kernel<<<HWPIX / 64, 256>>>(left, offx, offy, out);
}